// round 15
// baseline (speedup 1.0000x reference)
#include <cuda_runtime.h>
#include <math.h>

#define B   64
#define S   96
#define E   300
#define H   256
#define D   512
#define SEL 128
#define G5  1280
#define MLPD 1024
#define NC  3

#define CLG 16     // CTAs per group
#define NGR 8      // groups
#define NB  8      // batches per group
#define TPB 640
#define NS  97     // S + 1 spare slot

typedef unsigned long long ull;

__device__ __align__(16) float g_states[B][NS][D];
__device__ float g_logits0[B][S - 1];
__device__ float g_hroot[B][H];
__device__ float g_x1[B][MLPD];
__device__ float g_x2[B][MLPD];
__device__ __align__(16) ull g_part[2][NGR][NB][CLG][SEL];  // double-buffered partial logits
__device__ unsigned g_flag[NGR][CLG];   // zero at load; reset by epilogue
__device__ unsigned g_done[NGR];

__device__ __forceinline__ float sigf(float x) { return 1.0f / (1.0f + expf(-x)); }
__device__ __forceinline__ ull fma2(ull a, ull b, ull c) {
    ull d; asm("fma.rn.f32x2 %0, %1, %2, %3;" : "=l"(d) : "l"(a), "l"(b), "l"(c)); return d;
}
__device__ __forceinline__ ull add2(ull a, ull b) {
    ull d; asm("add.rn.f32x2 %0, %1, %2;" : "=l"(d) : "l"(a), "l"(b)); return d;
}
__device__ __forceinline__ ull pack2(float x, float y) {
    ull d; asm("mov.b64 %0, {%1, %2};" : "=l"(d) : "f"(x), "f"(y)); return d;
}
__device__ __forceinline__ float lo32(ull v) { return __uint_as_float((unsigned)v); }
__device__ __forceinline__ float hi32(ull v) { return __uint_as_float((unsigned)(v >> 32)); }

__device__ __forceinline__ void st_rel(unsigned* p, unsigned v) {
    asm volatile("st.release.gpu.global.u32 [%0], %1;" :: "l"(p), "r"(v) : "memory");
}
__device__ __forceinline__ unsigned ld_acq(const unsigned* p) {
    unsigned v;
    asm volatile("ld.acquire.gpu.global.u32 %0, [%1];" : "=r"(v) : "l"(p) : "memory");
    return v;
}

// ---- scan dynamic smem layout (bytes) ----
#define O_W     0        // float Wsm[512][84]            172032
#define O_XS2   172032   // ull  xs2[4][512]              16384
#define O_WS1A  188416   // float ws1a[16][128]           8192
#define O_WS1B  196608   // float ws1b[16][128]           8192
#define O_REDK  204800   // ull  redk[80][16]             10240
#define O_LG    215040   // float lg[8][96]               3072
#define O_PM    218112   // int  pm[8][96]                3072
#define O_CLCR  221184   // float clcr[8][2][16]          1024
#define O_BCS   222208   // float bcs[80]                 384
#define O_HLOC  222592   // float hloc[8][16]             512
#define O_LNB   223104   // float lnb[8][16]              512
#define O_RNB   223616   // float rnb[8][16]              512
#define O_BS1F  224128   // float bs1f[128]               512
#define O_WS2F  224640   // float ws2f[128]               512
#define O_RED   225152   // float red[8][2][2]            128
#define O_MISC  225280   // ints/floats                   512
#define SMEM_SZ 225792

// initsel dynamic smem: hs[17][256] floats + pht[512][8] ulls
#define ISEL_HS   0
#define ISEL_PHT  17408
#define ISEL_SMEM (17408 + 32768)

__global__ void prof_pad_kernel() {}

// ======================================================================
// encode: f32x2 packed (2 cols per ull), pre-splatted x in smem.
// ======================================================================
__global__ void encode_kernel(const int* __restrict__ sent, const float* __restrict__ emb,
                              const float* __restrict__ Wenc, const float* __restrict__ benc) {
    __shared__ __align__(16) ull xsh2[8 * E];
    __shared__ int tok[8];
    int row0 = blockIdx.x * 8, tid = threadIdx.x;
    if (tid < 8) tok[tid] = sent[row0 + tid];
    __syncthreads();
    for (int i = tid; i < 8 * E; i += 128) {
        int r = i / E, k = i - r * E;
        float v = emb[(long)tok[r] * E + k];
        xsh2[i] = pack2(v, v);
    }
    __syncthreads();
    int c = tid * 4;
    ull acc0[8], acc1[8];
#pragma unroll
    for (int r = 0; r < 8; r++) { acc0[r] = 0ull; acc1[r] = 0ull; }
    for (int k = 0; k < E; k += 2) {
        float4 wa = *(const float4*)&Wenc[k * D + c];
        float4 wb = *(const float4*)&Wenc[(k + 1) * D + c];
        ull wa0 = pack2(wa.x, wa.y), wa1 = pack2(wa.z, wa.w);
        ull wb0 = pack2(wb.x, wb.y), wb1 = pack2(wb.z, wb.w);
#pragma unroll
        for (int r = 0; r < 8; r++) {
            ulonglong2 xq = *(const ulonglong2*)&xsh2[r * E + k];
            acc0[r] = fma2(wa0, xq.x, acc0[r]);
            acc1[r] = fma2(wa1, xq.x, acc1[r]);
            acc0[r] = fma2(wb0, xq.y, acc0[r]);
            acc1[r] = fma2(wb1, xq.y, acc1[r]);
        }
    }
    float4 bv = *(const float4*)&benc[c];
#pragma unroll
    for (int r = 0; r < 8; r++) {
        float4 o;
        o.x = __fadd_rn(lo32(acc0[r]), bv.x);
        o.y = __fadd_rn(hi32(acc0[r]), bv.y);
        o.z = __fadd_rn(lo32(acc1[r]), bv.z);
        o.w = __fadd_rn(hi32(acc1[r]), bv.w);
        int gr = row0 + r, b = gr / S, s = gr - b * S;
        *(float4*)&g_states[b][s][c] = o;
    }
}

// ======================================================================
// initsel: k-outer, weights read ONCE; pairs (p, p+8) packed in f32x2.
// ======================================================================
__global__ void initsel_kernel(const float* __restrict__ Ws1, const float* __restrict__ bs1,
                               const float* __restrict__ Ws2, const float* __restrict__ bs2) {
    extern __shared__ char ism[];
    float* hs  = (float*)(ism + ISEL_HS);
    ull*   pht = (ull*)(ism + ISEL_PHT);
    __shared__ float red[16][4];
    int b = blockIdx.y, p0 = blockIdx.x * 16, tid = threadIdx.x;
    int nrows = min(17, S - p0);
    for (int i = tid; i < 17 * 256; i += 128) {
        int r = i >> 8, k = i & 255;
        hs[i] = (r < nrows) ? g_states[b][p0 + r][H + k] : 0.0f;
    }
    __syncthreads();
    for (int i = tid; i < 4096; i += 128) {
        int k = i >> 3, p = i & 7;
        int rr = (k >= 256) ? 1 : 0, kk = k & 255;
        pht[i] = pack2(hs[(p + rr) * 256 + kk], hs[(p + 8 + rr) * 256 + kk]);
    }
    __syncthreads();
    ull acc[8];
#pragma unroll
    for (int p = 0; p < 8; p++) acc[p] = 0ull;
    const float* wp = Ws1 + tid;
    for (int k = 0; k < 512; k++) {
        float w = wp[(size_t)k * SEL];
        ull ws = pack2(w, w);
        const ull* px = &pht[k * 8];
        ulonglong2 q0 = *(const ulonglong2*)&px[0];
        ulonglong2 q1 = *(const ulonglong2*)&px[2];
        ulonglong2 q2 = *(const ulonglong2*)&px[4];
        ulonglong2 q3 = *(const ulonglong2*)&px[6];
        acc[0] = fma2(ws, q0.x, acc[0]); acc[1] = fma2(ws, q0.y, acc[1]);
        acc[2] = fma2(ws, q1.x, acc[2]); acc[3] = fma2(ws, q1.y, acc[3]);
        acc[4] = fma2(ws, q2.x, acc[4]); acc[5] = fma2(ws, q2.y, acc[5]);
        acc[6] = fma2(ws, q3.x, acc[6]); acc[7] = fma2(ws, q3.y, acc[7]);
    }
    float b1 = bs1[tid], w2 = Ws2[tid];
    int lane = tid & 31, wrp = tid >> 5;
    int npairs = min(16, (S - 1) - p0);
#pragma unroll
    for (int p = 0; p < 16; p++) {
        float s = (p < 8) ? lo32(acc[p]) : hi32(acc[p - 8]);
        float y = tanhf(s + b1) * w2;
        for (int o = 16; o; o >>= 1) y += __shfl_xor_sync(0xffffffffu, y, o);
        if (lane == 0) red[p][wrp] = y;
    }
    __syncthreads();
    if (tid < npairs)
        g_logits0[b][p0 + tid] = red[tid][0] + red[tid][1] + red[tid][2] + red[tid][3] + bs2[0];
}

// ======================================================================
// Persistent scan: R14 structure, with (a) release/acquire flag barrier,
// (b) argmax fused into the step tail with inline logit substitution,
// (c) parity-indexed control buffers (sel/sL/sR/fsl).
// ======================================================================
__global__ void __launch_bounds__(TPB, 1)
scan_kernel(const float* __restrict__ Wc,  const float* __restrict__ bc,
            const float* __restrict__ Ws1, const float* __restrict__ bs1,
            const float* __restrict__ Ws2, const float* __restrict__ bs2) {
    extern __shared__ char dsm[];
    float* Wsm  = (float*)(dsm + O_W);
    ull*   xs2  = (ull*)(dsm + O_XS2);
    float* ws1a = (float*)(dsm + O_WS1A);
    float* ws1b = (float*)(dsm + O_WS1B);
    ull*   redk = (ull*)(dsm + O_REDK);
    float* lg   = (float*)(dsm + O_LG);
    int*   pmi  = (int*)(dsm + O_PM);
    float* clcr = (float*)(dsm + O_CLCR);
    float* bcs  = (float*)(dsm + O_BCS);
    float* hloc = (float*)(dsm + O_HLOC);
    float* lnb  = (float*)(dsm + O_LNB);
    float* rnb  = (float*)(dsm + O_RNB);
    float* bs1f = (float*)(dsm + O_BS1F);
    float* ws2f = (float*)(dsm + O_WS2F);
    float* red  = (float*)(dsm + O_RED);    // red[b*4 + w*2 + s]
    int*   misc = (int*)(dsm + O_MISC);
    int* sel2 = misc;         // [2][8]
    int* sLa2 = misc + 16;    // [2][8]
    int* sRa2 = misc + 32;    // [2][8]
    int* fsl2 = misc + 48;    // [2][8]
    int* frs  = misc + 64;    // [8]

    int tid = threadIdx.x;
    int r   = blockIdx.x & (CLG - 1);
    int gq  = blockIdx.x >> 4;
    int gb0 = gq * NB;

    // ---- one-time preloads ----
    for (int i = tid; i < 512 * 20; i += TPB) {
        int k = i / 20, q = i - k * 20;
        int g = q >> 2, u4 = (q & 3) * 4;
        float4 w = *(const float4*)&Wc[(size_t)k * G5 + g * 256 + r * 16 + u4];
        *(float4*)&Wsm[k * 84 + q * 4] = w;
    }
    for (int i = tid; i < 2048; i += TPB) {
        int u = i >> 7, j = i & 127;
        ws1a[i] = Ws1[(size_t)(r * 16 + u) * SEL + j];
        ws1b[i] = Ws1[(size_t)(256 + r * 16 + u) * SEL + j];
    }
    if (tid < 128) { bs1f[tid] = bs1[tid]; ws2f[tid] = Ws2[tid]; }
    if (tid < 80) {
        int g = tid >> 4, u = tid & 15;
        bcs[tid] = bc[g * 256 + r * 16 + u];
    }
    if (tid < 8) frs[tid] = 96;
    for (int i = tid; i < NB * (S - 1); i += TPB) {
        int b = i / (S - 1), j = i - b * (S - 1);
        lg[b * 96 + j] = g_logits0[gb0 + b][j];
    }
    for (int i = tid; i < NB * S; i += TPB) {
        int b = i / S, j = i - b * S;
        pmi[b * 96 + j] = j;
    }
    float bs2v = bs2[0];
    __syncthreads();

    // ---- bootstrap argmax (t=0, par=0, no substitution) ----
    if (tid < 256) {
        int b = tid >> 5, ln = tid & 31;
        float best = -1e30f; int bi = 0;
        for (int j = ln; j < S - 1; j += 32) {
            float v = lg[b * 96 + j];
            if (v > best) { best = v; bi = j; }
        }
        for (int o = 16; o; o >>= 1) {
            float ov = __shfl_xor_sync(0xffffffffu, best, o);
            int   oi = __shfl_xor_sync(0xffffffffu, bi, o);
            if (ov > best || (ov == best && oi < bi)) { best = ov; bi = oi; }
        }
        if (ln == 0) {
            int sl = pmi[b * 96 + bi], sr = pmi[b * 96 + bi + 1];
            sel2[b] = bi; sLa2[b] = sl; sRa2[b] = sr;
            fsl2[b] = frs[b];
            frs[b] = sr;
        }
    }
    __syncthreads();

    int wid = tid >> 5, lane = tid & 31;
    int cg  = wid % 5, ckb = wid / 5;
    int cks = lane >> 2, cq = lane & 3;
    int wbase = cg * 16 + cq * 4;

    for (int t = 0; t < S - 1; t++) {
        int n = S - t;
        int par = t & 1;
        int po = par * 8;
        ull* gp = &g_part[par][gq][0][0][0];

        // ---- staging: xs2 + clcr + neighbor slices ----
        if (tid < 512) {
            int p = tid >> 7, kq = (tid & 127) << 2;
            int b0 = 2 * p, b1 = 2 * p + 1;
            int slot0 = (kq < H) ? sLa2[po + b0] : sRa2[po + b0];
            int slot1 = (kq < H) ? sLa2[po + b1] : sRa2[po + b1];
            int col = (kq < H) ? (H + kq) : kq;
            float4 a = __ldcg((const float4*)&g_states[gb0 + b0][slot0][col]);
            float4 c = __ldcg((const float4*)&g_states[gb0 + b1][slot1][col]);
            xs2[p * 512 + kq]     = pack2(a.x, c.x);
            xs2[p * 512 + kq + 1] = pack2(a.y, c.y);
            xs2[p * 512 + kq + 2] = pack2(a.z, c.z);
            xs2[p * 512 + kq + 3] = pack2(a.w, c.w);
        } else {
            int i0 = (tid - 512) * 2;
#pragma unroll
            for (int s = 0; s < 2; s++) {
                int i = i0 + s;
                int b = i >> 5, half = (i >> 4) & 1, u = i & 15;
                clcr[(b * 2 + half) * 16 + u] =
                    __ldcg(&g_states[gb0 + b][half ? sRa2[po + b] : sLa2[po + b]][r * 16 + u]);
            }
        }
        if (tid < 256) {
            int b = tid >> 5, rest = tid & 31;
            int half = rest >> 4, u = rest & 15;
            int idx = sel2[po + b];
            float v = 0.f;
            if (half == 0) {
                if (idx >= 1)
                    v = __ldcg(&g_states[gb0 + b][pmi[b * 96 + idx - 1]][H + r * 16 + u]);
                lnb[b * 16 + u] = v;
            } else {
                if (idx <= n - 3)
                    v = __ldcg(&g_states[gb0 + b][pmi[b * 96 + idx + 2]][H + r * 16 + u]);
                rnb[b * 16 + u] = v;
            }
        }
        __syncthreads();

        // ---- compose from SMEM weights ----
        {
            ull acc[16];
#pragma unroll
            for (int i = 0; i < 16; i++) acc[i] = 0ull;
#pragma unroll 4
            for (int m = 0; m < 16; m++) {
                int k = ckb * 128 + m * 8 + cks;
                float4 w4 = *(const float4*)&Wsm[k * 84 + wbase];
                ull x0 = xs2[k], x1 = xs2[512 + k], x2 = xs2[1024 + k], x3 = xs2[1536 + k];
                ull w;
                w = pack2(w4.x, w4.x);
                acc[0] = fma2(w, x0, acc[0]); acc[1] = fma2(w, x1, acc[1]);
                acc[2] = fma2(w, x2, acc[2]); acc[3] = fma2(w, x3, acc[3]);
                w = pack2(w4.y, w4.y);
                acc[4] = fma2(w, x0, acc[4]); acc[5] = fma2(w, x1, acc[5]);
                acc[6] = fma2(w, x2, acc[6]); acc[7] = fma2(w, x3, acc[7]);
                w = pack2(w4.z, w4.z);
                acc[8] = fma2(w, x0, acc[8]); acc[9] = fma2(w, x1, acc[9]);
                acc[10] = fma2(w, x2, acc[10]); acc[11] = fma2(w, x3, acc[11]);
                w = pack2(w4.w, w4.w);
                acc[12] = fma2(w, x0, acc[12]); acc[13] = fma2(w, x1, acc[13]);
                acc[14] = fma2(w, x2, acc[14]); acc[15] = fma2(w, x3, acc[15]);
            }
#pragma unroll
            for (int i = 0; i < 16; i++) {
                acc[i] = add2(acc[i], __shfl_xor_sync(0xffffffffu, acc[i], 4));
                acc[i] = add2(acc[i], __shfl_xor_sync(0xffffffffu, acc[i], 8));
                acc[i] = add2(acc[i], __shfl_xor_sync(0xffffffffu, acc[i], 16));
            }
            if (cks == 0) {
                ull* dst = &redk[(size_t)((ckb * 5 + cg) * 4 + cq) * 16];
#pragma unroll
                for (int i = 0; i < 16; i++) dst[i] = acc[i];
            }
        }
        __syncthreads();

        // ---- gates (tid<128) overlapped with shift-read (tid>=128) ----
        int spv0 = 0, swp0 = 0, swl0 = 0; float slv0 = 0.f; int sb0 = 0, sj0 = 0;
        int spv1 = 0, swp1 = 0, swl1 = 0; float slv1 = 0.f; int sb1 = 0, sj1 = 0;
        if (tid < 128) {
            int b = tid >> 4, u = tid & 15;
            int ucq = u >> 2, uc = u & 3, p = b >> 1, half = b & 1;
            float gate[5];
#pragma unroll
            for (int g = 0; g < 5; g++) {
                float s = 0.f;
#pragma unroll
                for (int kb = 0; kb < 4; kb++) {
                    ull v = redk[(size_t)((kb * 5 + g) * 4 + ucq) * 16 + uc * 4 + p];
                    s += half ? hi32(v) : lo32(v);
                }
                gate[g] = s + bcs[g * 16 + u];
            }
            int gb = gb0 + b, h = r * 16 + u;
            float cl = clcr[(b * 2 + 0) * 16 + u];
            float cr = clcr[(b * 2 + 1) * 16 + u];
            float cc = sigf(gate[1]) * cl + sigf(gate[2]) * cr + sigf(gate[0]) * tanhf(gate[4]);
            float hp = sigf(gate[3]) * tanhf(cc);
            g_states[gb][fsl2[po + b]][h]     = cc;
            g_states[gb][fsl2[po + b]][H + h] = hp;
            hloc[b * 16 + u] = hp;
        } else {
            int ii0 = tid - 128, ii1 = ii0 + 512;
            sb0 = ii0 / 96; sj0 = ii0 - sb0 * 96;
            {
                int idx = sel2[po + sb0];
                if (sj0 >= idx + 1 && sj0 <= n - 2) { spv0 = pmi[sb0 * 96 + sj0 + 1]; swp0 = 1; }
                if (sj0 >= idx + 1 && sj0 <= n - 3) { slv0 = lg[sb0 * 96 + sj0 + 1]; swl0 = 1; }
            }
            if (ii1 < NB * 96) {
                sb1 = ii1 / 96; sj1 = ii1 - sb1 * 96;
                int idx = sel2[po + sb1];
                if (sj1 >= idx + 1 && sj1 <= n - 2) { spv1 = pmi[sb1 * 96 + sj1 + 1]; swp1 = 1; }
                if (sj1 >= idx + 1 && sj1 <= n - 3) { slv1 = lg[sb1 * 96 + sj1 + 1]; swl1 = 1; }
            }
        }
        __syncthreads();

        // ---- shift-write + phase5 partials ----
        if (tid >= 128) {
            if (swp0) pmi[sb0 * 96 + sj0] = spv0;
            if (swl0) lg[sb0 * 96 + sj0] = slv0;
            if (swp1) pmi[sb1 * 96 + sj1] = spv1;
            if (swl1) lg[sb1 * 96 + sj1] = slv1;
        }
        if (tid < NB) pmi[tid * 96 + sel2[po + tid]] = fsl2[po + tid];
        if (tid < 512) {
            int b = tid >> 6, j = (tid & 63) * 2;
            ull a0 = 0ull, a1 = 0ull;
#pragma unroll 4
            for (int u = 0; u < 16; u++) {
                float ln = lnb[b * 16 + u];
                float hp = hloc[b * 16 + u];
                float rn = rnb[b * 16 + u];
                ull xa = pack2(ln, hp);
                ull xb = pack2(hp, rn);
                float2 wa = *(const float2*)&ws1a[u * 128 + j];
                float2 wb = *(const float2*)&ws1b[u * 128 + j];
                a0 = fma2(pack2(wa.x, wa.x), xa, a0);
                a0 = fma2(pack2(wb.x, wb.x), xb, a0);
                a1 = fma2(pack2(wa.y, wa.y), xa, a1);
                a1 = fma2(pack2(wb.y, wb.y), xb, a1);
            }
            ulonglong2 st; st.x = a0; st.y = a1;
            *(ulonglong2*)&gp[(size_t)(b * CLG + r) * SEL + j] = st;
        }

        // ---- release/acquire flag barrier ----
        __syncthreads();
        if (tid == 0) st_rel(&g_flag[gq][r], (unsigned)(t + 1));
        if (tid < CLG) {
            while (ld_acq(&g_flag[gq][tid]) <= (unsigned)t) {}
        }
        __syncthreads();

        // ---- replicated logit reconstruction ----
        if (tid < 512) {
            int b = tid >> 6, j0 = tid & 63;
            const ull* src = &gp[(size_t)(b * CLG) * SEL + j0 * 2];
            ull ax0 = 0ull, ax1 = 0ull, ax2 = 0ull, ax3 = 0ull;
            ull ay0 = 0ull, ay1 = 0ull, ay2 = 0ull, ay3 = 0ull;
#pragma unroll
            for (int rr = 0; rr < CLG; rr += 4) {
                ulonglong2 q0 = __ldcg((const ulonglong2*)(src + (size_t)(rr + 0) * SEL));
                ulonglong2 q1 = __ldcg((const ulonglong2*)(src + (size_t)(rr + 1) * SEL));
                ulonglong2 q2 = __ldcg((const ulonglong2*)(src + (size_t)(rr + 2) * SEL));
                ulonglong2 q3 = __ldcg((const ulonglong2*)(src + (size_t)(rr + 3) * SEL));
                ax0 = add2(ax0, q0.x); ay0 = add2(ay0, q0.y);
                ax1 = add2(ax1, q1.x); ay1 = add2(ay1, q1.y);
                ax2 = add2(ax2, q2.x); ay2 = add2(ay2, q2.y);
                ax3 = add2(ax3, q3.x); ay3 = add2(ay3, q3.y);
            }
            ull vx = add2(add2(ax0, ax1), add2(ax2, ax3));
            ull vy = add2(add2(ay0, ay1), add2(ay2, ay3));
            float2 b2 = *(const float2*)&bs1f[j0 * 2];
            float2 w2 = *(const float2*)&ws2f[j0 * 2];
            float yA = tanhf(lo32(vx) + b2.x) * w2.x + tanhf(lo32(vy) + b2.y) * w2.y;
            float yB = tanhf(hi32(vx) + b2.x) * w2.x + tanhf(hi32(vy) + b2.y) * w2.y;
#pragma unroll
            for (int o = 1; o < 32; o <<= 1) {
                yA += __shfl_xor_sync(0xffffffffu, yA, o);
                yB += __shfl_xor_sync(0xffffffffu, yB, o);
            }
            if ((tid & 31) == 0) {
                int w = (tid >> 5) & 1;
                red[(b * 2 + w) * 2 + 0] = yA;
                red[(b * 2 + w) * 2 + 1] = yB;
            }
        }
        __syncthreads();

        // ---- fused: next-step argmax (inline substitution) + lg write ----
        if (tid < 256) {
            int b = tid >> 5, ln = tid & 31;
            int sc = sel2[po + b];
            float nA = red[b * 4 + 0] + red[b * 4 + 2] + bs2v;   // q0 value
            float nB = red[b * 4 + 1] + red[b * 4 + 3] + bs2v;   // q1 value
            int q0 = sc - 1, q1 = sc;
            int np2 = n - 2;      // pair count at step t+1
            float best = -1e30f; int bi = 0;
            for (int j = ln; j < np2; j += 32) {
                float v = lg[b * 96 + j];
                if (j == q0) v = nA;
                if (j == q1) v = nB;
                if (v > best) { best = v; bi = j; }
            }
            for (int o = 16; o; o >>= 1) {
                float ov = __shfl_xor_sync(0xffffffffu, best, o);
                int   oi = __shfl_xor_sync(0xffffffffu, bi, o);
                if (ov > best || (ov == best && oi < bi)) { best = ov; bi = oi; }
            }
            if (ln == 0) {
                int pn = (po ^ 8);
                int sl = pmi[b * 96 + bi], sr = pmi[b * 96 + bi + 1];
                sel2[pn + b] = bi; sLa2[pn + b] = sl; sRa2[pn + b] = sr;
                fsl2[pn + b] = frs[b];
                frs[b] = sr;
            }
        } else if (tid < 272) {
            int i = tid - 256;
            int b = i >> 1, s = i & 1;
            int q = sel2[po + b] - 1 + s;
            if (q >= 0 && q <= n - 3)
                lg[b * 96 + q] = red[b * 4 + s] + red[b * 4 + 2 + s] + bs2v;
        }
        __syncthreads();
    }

    // ---- root hidden ----
    if (tid < 128) {
        int b = tid >> 4, u = tid & 15;
        g_hroot[gb0 + b][r * 16 + u] =
            __ldcg(&g_states[gb0 + b][pmi[b * 96]][H + r * 16 + u]);
    }

    // ---- epilogue: reset flags for next graph replay ----
    __syncthreads();
    if (tid == 0) {
        __threadfence();
        atomicAdd(&g_done[gq], 1u);
        if (r == 0) {
            while (atomicAdd(&g_done[gq], 0u) < CLG) {}
            for (int i = 0; i < CLG; i++) g_flag[gq][i] = 0u;
            g_done[gq] = 0u;
            __threadfence();
        }
    }
}

// ======================================================================
// MLP: batch-tiled, k-split, batch-pair f32x2
// ======================================================================
__global__ void mlp_l1(const float* __restrict__ Wm1, const float* __restrict__ bm1) {
    __shared__ __align__(16) float xt[H * 8];
    __shared__ ull part2[4 * 64 * 4];
    int bx = blockIdx.x, by = blockIdx.y, tid = threadIdx.x;
    for (int i = tid; i < H * 8; i += 256) {
        int k = i >> 3, b = i & 7;
        xt[i] = g_hroot[by * 8 + b][k];
    }
    __syncthreads();
    int col = tid & 63, ks = tid >> 6;
    int c = bx * 64 + col;
    ull acc[4];
#pragma unroll
    for (int q = 0; q < 4; q++) acc[q] = 0ull;
    for (int k = ks * 64; k < ks * 64 + 64; k++) {
        float w = Wm1[(size_t)k * MLPD + c];
        ull ws = pack2(w, w);
        const ull* xp = (const ull*)&xt[k * 8];
        acc[0] = fma2(ws, xp[0], acc[0]);
        acc[1] = fma2(ws, xp[1], acc[1]);
        acc[2] = fma2(ws, xp[2], acc[2]);
        acc[3] = fma2(ws, xp[3], acc[3]);
    }
#pragma unroll
    for (int q = 0; q < 4; q++) part2[(ks * 64 + col) * 4 + q] = acc[q];
    __syncthreads();
    for (int i = tid; i < 512; i += 256) {
        int cc = i >> 3, b = i & 7;
        int q = b >> 1, half = b & 1;
        float s = 0.f;
#pragma unroll
        for (int kk = 0; kk < 4; kk++) {
            ull v = part2[(kk * 64 + cc) * 4 + q];
            s += half ? hi32(v) : lo32(v);
        }
        g_x1[by * 8 + b][bx * 64 + cc] = fmaxf(s + bm1[bx * 64 + cc], 0.0f);
    }
}

__global__ void mlp_l2(const float* __restrict__ Wm2, const float* __restrict__ bm2) {
    __shared__ __align__(16) float xt[MLPD * 8];
    __shared__ ull part2[4 * 64 * 4];
    int bx = blockIdx.x, by = blockIdx.y, tid = threadIdx.x;
    for (int i = tid; i < MLPD * 8; i += 256) {
        int b = i >> 10, k = i & 1023;
        xt[k * 8 + b] = g_x1[by * 8 + b][k];
    }
    __syncthreads();
    int col = tid & 63, ks = tid >> 6;
    int c = bx * 64 + col;
    ull acc[4];
#pragma unroll
    for (int q = 0; q < 4; q++) acc[q] = 0ull;
    for (int k = ks * 256; k < ks * 256 + 256; k++) {
        float w = Wm2[(size_t)k * MLPD + c];
        ull ws = pack2(w, w);
        const ull* xp = (const ull*)&xt[k * 8];
        acc[0] = fma2(ws, xp[0], acc[0]);
        acc[1] = fma2(ws, xp[1], acc[1]);
        acc[2] = fma2(ws, xp[2], acc[2]);
        acc[3] = fma2(ws, xp[3], acc[3]);
    }
#pragma unroll
    for (int q = 0; q < 4; q++) part2[(ks * 64 + col) * 4 + q] = acc[q];
    __syncthreads();
    for (int i = tid; i < 512; i += 256) {
        int cc = i >> 3, b = i & 7;
        int q = b >> 1, half = b & 1;
        float s = 0.f;
#pragma unroll
        for (int kk = 0; kk < 4; kk++) {
            ull v = part2[(kk * 64 + cc) * 4 + q];
            s += half ? hi32(v) : lo32(v);
        }
        g_x2[by * 8 + b][bx * 64 + cc] = fmaxf(s + bm2[bx * 64 + cc], 0.0f);
    }
}

__global__ void mlp_l3(const float* __restrict__ Wout, const float* __restrict__ bout,
                       float* __restrict__ out) {
    __shared__ float red[4][NC];
    int b = blockIdx.x, tid = threadIdx.x;
    float p0 = 0.f, p1 = 0.f, p2 = 0.f;
    for (int k = tid; k < MLPD; k += 128) {
        float xv = g_x2[b][k];
        p0 = __fmaf_rn(xv, Wout[k * NC + 0], p0);
        p1 = __fmaf_rn(xv, Wout[k * NC + 1], p1);
        p2 = __fmaf_rn(xv, Wout[k * NC + 2], p2);
    }
    for (int o = 16; o; o >>= 1) {
        p0 += __shfl_xor_sync(0xffffffffu, p0, o);
        p1 += __shfl_xor_sync(0xffffffffu, p1, o);
        p2 += __shfl_xor_sync(0xffffffffu, p2, o);
    }
    int lane = tid & 31, wrp = tid >> 5;
    if (lane == 0) { red[wrp][0] = p0; red[wrp][1] = p1; red[wrp][2] = p2; }
    __syncthreads();
    if (tid < NC) {
        float s = bout[tid];
        for (int w = 0; w < 4; w++) s += red[w][tid];
        out[b * NC + tid] = s;
    }
}

// ======================================================================
extern "C" void kernel_launch(void* const* d_in, const int* in_sizes, int n_in,
                              void* d_out, int out_size) {
    const int*   sent = (const int*)d_in[0];
    const float* emb  = (const float*)d_in[2];
    const float* Wenc = (const float*)d_in[3];
    const float* benc = (const float*)d_in[4];
    const float* Wc   = (const float*)d_in[5];
    const float* bc   = (const float*)d_in[6];
    const float* Ws1  = (const float*)d_in[7];
    const float* bs1  = (const float*)d_in[8];
    const float* Ws2  = (const float*)d_in[9];
    const float* bs2  = (const float*)d_in[10];
    const float* Wm1  = (const float*)d_in[11];
    const float* bm1  = (const float*)d_in[12];
    const float* Wm2  = (const float*)d_in[13];
    const float* bm2  = (const float*)d_in[14];
    const float* Wout = (const float*)d_in[15];
    const float* bout = (const float*)d_in[16];

    static int smem_set = 0;
    if (!smem_set) {
        cudaFuncSetAttribute(scan_kernel, cudaFuncAttributeMaxDynamicSharedMemorySize, SMEM_SZ);
        cudaFuncSetAttribute(initsel_kernel, cudaFuncAttributeMaxDynamicSharedMemorySize, ISEL_SMEM);
        smem_set = 1;
    }

    prof_pad_kernel<<<1, 32>>>();   // keeps ncu's profiled slot on scan_kernel
    encode_kernel<<<768, 128>>>(sent, emb, Wenc, benc);
    initsel_kernel<<<dim3(6, 64), 128, ISEL_SMEM>>>(Ws1, bs1, Ws2, bs2);
    scan_kernel<<<NGR * CLG, TPB, SMEM_SZ>>>(Wc, bc, Ws1, bs1, Ws2, bs2);
    mlp_l1<<<dim3(16, 8), 256>>>(Wm1, bm1);
    mlp_l2<<<dim3(16, 8), 256>>>(Wm2, bm2);
    mlp_l3<<<B, 128>>>(Wout, bout, (float*)d_out);
}